// round 6
// baseline (speedup 1.0000x reference)
#include <cuda_runtime.h>
#include <math.h>

// ---------------- model constants ----------------
#define D_    1024
#define V_    32000
#define DFF_  4096
#define H_    16
#define T_    2048
#define HD_   64
#define CAP_  512
#define NHOPS_ 4

// ---------------- workspace ----------------
constexpr size_t SZ_TD   = (size_t)T_ * D_;
constexpr size_t OFF_H   = 0;
constexpr size_t OFF_XN  = OFF_H   + SZ_TD;
constexpr size_t OFF_Q   = OFF_XN  + SZ_TD;
constexpr size_t OFF_K   = OFF_Q   + SZ_TD;
constexpr size_t OFF_V   = OFF_K   + SZ_TD;
constexpr size_t OFF_AO  = OFF_V   + SZ_TD;
constexpr size_t OFF_FFN = OFF_AO  + SZ_TD;
constexpr size_t OFF_SC  = OFF_FFN + (size_t)T_ * DFF_;
constexpr size_t OFF_XIN = OFF_SC  + (size_t)H_ * T_ * T_;
constexpr size_t OFF_EOUT= OFF_XIN + (size_t)8 * CAP_ * D_;
constexpr size_t OFF_COS = OFF_EOUT+ (size_t)8 * CAP_ * D_;
constexpr size_t OFF_SIN = OFF_COS + (size_t)T_ * HD_;
constexpr size_t OFF_COSR= OFF_SIN + (size_t)T_ * HD_;
constexpr size_t OFF_SINR= OFF_COSR+ (size_t)8 * CAP_ * HD_;
constexpr size_t OFF_LG  = OFF_SINR+ (size_t)8 * CAP_ * HD_;
constexpr size_t OFF_RHO = OFF_LG  + (size_t)T_ * 9;
constexpr size_t WS_TOTAL= OFF_RHO + (size_t)T_;
__device__ float g_ws[WS_TOTAL];

// double-precision prefix sums of cos/sin: (T+1) x HD each
constexpr size_t OFF_PC = 0;
constexpr size_t OFF_PS = (size_t)(T_ + 1) * HD_;
constexpr size_t WSD_TOTAL = 2 * (size_t)(T_ + 1) * HD_;
__device__ double g_wsd[WSD_TOTAL];

constexpr size_t IOFF_SEL   = 0;                      // T*2
constexpr size_t IOFF_STOK  = IOFF_SEL  + 2 * T_;     // 9*CAP
constexpr size_t IOFF_TSLOT = IOFF_STOK + 9 * CAP_;   // T*2
constexpr size_t IOFF_ECNT  = IOFF_TSLOT + 2 * T_;    // 9
constexpr size_t IOFF_EOV   = IOFF_ECNT + 9;          // 9
constexpr size_t WSI_TOTAL  = IOFF_EOV + 9;
__device__ int g_wsi[WSI_TOTAL];

// ---------------- generic strided-batched SGEMM ----------------
// C = alpha * A(MxK) * B    (TB ? B is NxK row-major, C=A*B^T : B is KxN row-major)
// ACC: C += result
template<bool TB, bool ACC>
__global__ void sgemm_k(const float* __restrict__ A, const float* __restrict__ B,
                        float* __restrict__ C,
                        int M, int N, int K, int lda, int ldb, int ldc,
                        long long sA, long long sB, long long sC, float alpha)
{
    __shared__ float As[16][128];
    __shared__ float Bs[16][128];
    int b = blockIdx.z;
    A += (size_t)b * sA; B += (size_t)b * sB; C += (size_t)b * sC;
    int m0 = blockIdx.y * 128, n0 = blockIdx.x * 128;
    int tid = threadIdx.x;
    int tx = tid & 15, ty = tid >> 4;
    float acc[8][8];
    #pragma unroll
    for (int i = 0; i < 8; i++)
        #pragma unroll
        for (int j = 0; j < 8; j++) acc[i][j] = 0.f;

    for (int k0 = 0; k0 < K; k0 += 16) {
        #pragma unroll
        for (int i = 0; i < 8; i++) {
            int idx = tid + i * 256;
            int k = idx & 15, m = idx >> 4;
            int gm = m0 + m, gk = k0 + k;
            As[k][m] = (gm < M && gk < K) ? A[(long long)gm * lda + gk] : 0.f;
        }
        #pragma unroll
        for (int i = 0; i < 8; i++) {
            int idx = tid + i * 256;
            if (!TB) {
                int n = idx & 127, k = idx >> 7;
                int gk = k0 + k, gn = n0 + n;
                Bs[k][n] = (gk < K && gn < N) ? B[(long long)gk * ldb + gn] : 0.f;
            } else {
                int k = idx & 15, n = idx >> 4;
                int gn = n0 + n, gk = k0 + k;
                Bs[k][n] = (gn < N && gk < K) ? B[(long long)gn * ldb + gk] : 0.f;
            }
        }
        __syncthreads();
        #pragma unroll
        for (int k = 0; k < 16; k++) {
            float ra[8], rb[8];
            #pragma unroll
            for (int i = 0; i < 8; i++) ra[i] = As[k][ty * 8 + i];
            #pragma unroll
            for (int i = 0; i < 8; i++) rb[i] = Bs[k][tx * 8 + i];
            #pragma unroll
            for (int i = 0; i < 8; i++)
                #pragma unroll
                for (int j = 0; j < 8; j++)
                    acc[i][j] += ra[i] * rb[j];
        }
        __syncthreads();
    }
    #pragma unroll
    for (int i = 0; i < 8; i++) {
        int gm = m0 + ty * 8 + i;
        if (gm >= M) continue;
        #pragma unroll
        for (int j = 0; j < 8; j++) {
            int gn = n0 + tx * 8 + j;
            if (gn >= N) continue;
            long long off = (long long)gm * ldc + gn;
            float v = alpha * acc[i][j];
            if (ACC) C[off] += v; else C[off] = v;
        }
    }
}

// ---------------- small kernels ----------------
__global__ void rope_tab_k(float* __restrict__ cs, float* __restrict__ sn)
{
    int t = blockIdx.x, i = threadIdx.x;           // i in [0,64)
    int j = i & 31;
    float ex = (float)(2 * j) / 64.0f;
    float inv = (float)(1.0 / pow(10000.0, (double)ex));
    float ang = (float)t * inv;
    cs[t * HD_ + i] = cosf(ang);
    sn[t * HD_ + i] = sinf(ang);
}

// prefix sums of cos/sin over tokens, double precision. <<<1, 64>>>
__global__ void prefix_k(const float* __restrict__ cs, const float* __restrict__ sn,
                         double* __restrict__ pc, double* __restrict__ ps)
{
    int d = threadIdx.x;
    double a = 0.0, b = 0.0;
    pc[d] = 0.0; ps[d] = 0.0;
    for (int t = 0; t < T_; t++) {
        a += (double)cs[t * HD_ + d];
        b += (double)sn[t * HD_ + d];
        pc[(t + 1) * HD_ + d] = a;
        ps[(t + 1) * HD_ + d] = b;
    }
}

__global__ void embed_k(const int* __restrict__ ids, const float* __restrict__ em,
                        float* __restrict__ h)
{
    int t = blockIdx.x;
    long long r = ids[t];
    const float* src = em + r * D_;
    float* dst = h + (size_t)t * D_;
    for (int d = threadIdx.x; d < D_; d += 256) dst[d] = src[d];
}

__global__ void rmsnorm_k(const float* __restrict__ x, const float* __restrict__ ln,
                          float* __restrict__ y)
{
    int row = blockIdx.x;
    const float* xr = x + (size_t)row * D_;
    float* yr = y + (size_t)row * D_;
    __shared__ float red[256];
    float s = 0.f;
    for (int d = threadIdx.x; d < D_; d += 256) { float v = xr[d]; s += v * v; }
    red[threadIdx.x] = s; __syncthreads();
    for (int st = 128; st > 0; st >>= 1) {
        if (threadIdx.x < st) red[threadIdx.x] += red[threadIdx.x + st];
        __syncthreads();
    }
    float r = rsqrtf(red[0] / (float)D_ + 1e-6f);
    for (int d = threadIdx.x; d < D_; d += 256) yr[d] = xr[d] * r * ln[d];
}

__global__ void rope_k(float* __restrict__ q, float* __restrict__ k,
                       const float* __restrict__ cs, const float* __restrict__ sn)
{
    int row = blockIdx.x;
    int tid = threadIdx.x;                 // 512 = 16 heads * 32
    int h = tid >> 5, i = tid & 31;
    float c1 = cs[row * HD_ + i],      s1 = sn[row * HD_ + i];
    float c2 = cs[row * HD_ + i + 32], s2 = sn[row * HD_ + i + 32];
    long long base = (long long)row * D_ + h * HD_ + i;
    float q0 = q[base], q1 = q[base + 32];
    q[base]      = q0 * c1 - q1 * s1;
    q[base + 32] = q1 * c2 + q0 * s2;
    float k0 = k[base], k1 = k[base + 32];
    k[base]      = k0 * c1 - k1 * s1;
    k[base + 32] = k1 * c2 + k0 * s2;
}

__global__ void softmax_causal_k(float* __restrict__ sc, int S)
{
    int i = blockIdx.x, h = blockIdx.y;
    float* row = sc + ((size_t)h * S + i) * (size_t)S;
    int valid = i + 1;
    __shared__ float red[256];
    int tid = threadIdx.x;
    float m = -1e30f;
    for (int j = tid; j < valid; j += 256) m = fmaxf(m, row[j]);
    red[tid] = m; __syncthreads();
    for (int st = 128; st > 0; st >>= 1) {
        if (tid < st) red[tid] = fmaxf(red[tid], red[tid + st]);
        __syncthreads();
    }
    m = red[0]; __syncthreads();
    float sum = 0.f;
    for (int j = tid; j < valid; j += 256) { float e = expf(row[j] - m); row[j] = e; sum += e; }
    red[tid] = sum; __syncthreads();
    for (int st = 128; st > 0; st >>= 1) {
        if (tid < st) red[tid] += red[tid + st];
        __syncthreads();
    }
    float inv = 1.0f / red[0];
    for (int j = tid; j < valid; j += 256) row[j] *= inv;
    for (int j = valid + tid; j < S; j += 256) row[j] = 0.f;
}

__global__ void gelu_k(float* __restrict__ x, long long n)
{
    for (long long i = blockIdx.x * (long long)blockDim.x + threadIdx.x; i < n;
         i += (long long)gridDim.x * blockDim.x) {
        float v = x[i];
        float t = tanhf(0.7978845608028654f * (v + 0.044715f * v * v * v));
        x[i] = 0.5f * v * (1.f + t);
    }
}

__global__ void top2_k(const float* __restrict__ lg, int* __restrict__ sel,
                       float* __restrict__ rho)
{
    int t = blockIdx.x * blockDim.x + threadIdx.x;
    if (t >= T_) return;
    const float* l = lg + (size_t)t * 9;
    int e0 = 0; float b0 = l[0];
    for (int e = 1; e < 9; e++) if (l[e] > b0) { b0 = l[e]; e0 = e; }
    int e1 = -1; float b1 = -1e30f;
    for (int e = 0; e < 9; e++) { if (e == e0) continue; if (l[e] > b1) { b1 = l[e]; e1 = e; } }
    sel[2 * t] = e0; sel[2 * t + 1] = e1;
    rho[t] = 0.5f * (float)((e0 < 8 ? 1 : 0) + (e1 < 8 ? 1 : 0));
}

__global__ void clear_k(int* __restrict__ p, int n)
{
    int i = blockIdx.x * blockDim.x + threadIdx.x;
    if (i < n) p[i] = -1;
}

// per-expert sequential scan: slot tokens, token->slot map, total count, first
// overflow token (the token with rank == CAP, i.e. (CAP+1)-th selected).
__global__ void scan_k(const int* __restrict__ sel, int* __restrict__ stok,
                       int* __restrict__ tslot, int* __restrict__ ecnt,
                       int* __restrict__ eov)
{
    int e = threadIdx.x;
    if (e >= 9) return;
    int cnt = 0, ov = T_;
    for (int t = 0; t < T_; t++) {
        #pragma unroll
        for (int j = 0; j < 2; j++) {
            if (sel[2 * t + j] == e) {
                int r = cnt++;
                if (r < CAP_) { stok[e * CAP_ + r] = t; tslot[2 * t + j] = r; }
                else          { tslot[2 * t + j] = -1; if (r == CAP_) ov = t; }
            }
        }
    }
    ecnt[e] = cnt;
    eov[e] = ov;
}

__global__ void gather_k(const float* __restrict__ h, const int* __restrict__ stok,
                         float* __restrict__ xin)
{
    int row = blockIdx.x;                 // 0..8*CAP-1, experts 0..7
    int tok = stok[row];
    float* xo = xin + (size_t)row * D_;
    if (tok >= 0) {
        const float* hr = h + (size_t)tok * D_;
        for (int d = threadIdx.x; d < D_; d += 256) xo[d] = 0.5f * hr[d];
    } else {
        for (int d = threadIdx.x; d < D_; d += 256) xo[d] = 0.f;
    }
}

// cos_r/sin_r per the reference's raw-slot einsum: slot is NOT a permutation.
// Every token contributes to the slot equal to clip(rank, 0, CAP-1) as long as
// rank < CAP, where rank[t] = (#selected tokens <= t) - 1. So slot c sums
// cos/sin over a token interval [start, end):
//   c == 0           : start = 0 (covers rank == -1 region too)
//   c  > 0           : start = stok[c]
//   end = stok[c+1] if c+1 < min(m, CAP); eov if c+1 == CAP < m; else T.
// Empty expert (m == 0): slot 0 sums ALL tokens.
__global__ void fill_cossin_k(const int* __restrict__ stok, const int* __restrict__ ecnt,
                              const int* __restrict__ eov,
                              const double* __restrict__ pc, const double* __restrict__ ps,
                              float* __restrict__ csr, float* __restrict__ snr)
{
    int row = blockIdx.x;               // 8*CAP
    int e = row / CAP_, c = row % CAP_;
    int d = threadIdx.x;                // 64
    int m = ecnt[e];
    int mc = m < CAP_ ? m : CAP_;
    bool active = (c < mc) || (m == 0 && c == 0);
    if (!active) {
        csr[row * HD_ + d] = 0.f;
        snr[row * HD_ + d] = 0.f;
        return;
    }
    int start = (c == 0) ? 0 : stok[e * CAP_ + c];
    int end;
    if (m == 0)            end = T_;
    else if (c + 1 < m)    end = (c + 1 < CAP_) ? stok[e * CAP_ + c + 1] : eov[e];
    else                   end = T_;
    csr[row * HD_ + d] = (float)(pc[end * HD_ + d] - pc[start * HD_ + d]);
    snr[row * HD_ + d] = (float)(ps[end * HD_ + d] - ps[start * HD_ + d]);
}

__global__ void scale_k(float* __restrict__ h, const float* __restrict__ rho)
{
    int t = blockIdx.x;
    float f = 1.0f - rho[t];
    float* hr = h + (size_t)t * D_;
    for (int d = threadIdx.x; d < D_; d += 256) hr[d] *= f;
}

__global__ void combine_k(float* __restrict__ h, const float* __restrict__ eout,
                          const int* __restrict__ sel, const int* __restrict__ tslot)
{
    int t = blockIdx.x;
    float* hr = h + (size_t)t * D_;
    #pragma unroll
    for (int j = 0; j < 2; j++) {
        int e = sel[2 * t + j];
        int s = tslot[2 * t + j];
        if (e < 8 && s >= 0) {
            const float* src = eout + ((size_t)e * CAP_ + s) * D_;
            for (int d = threadIdx.x; d < D_; d += 256) hr[d] += 0.5f * src[d];
        }
    }
}

// ---------------- host helpers ----------------
static void gemm(bool tb, bool acc, const float* A, const float* B, float* C,
                 int M, int N, int K, int lda, int ldb, int ldc,
                 long long sA, long long sB, long long sC, int batch, float alpha)
{
    dim3 g((N + 127) / 128, (M + 127) / 128, batch), b(256);
    if (!tb && !acc)      sgemm_k<false, false><<<g, b>>>(A, B, C, M, N, K, lda, ldb, ldc, sA, sB, sC, alpha);
    else if (!tb && acc)  sgemm_k<false, true ><<<g, b>>>(A, B, C, M, N, K, lda, ldb, ldc, sA, sB, sC, alpha);
    else if (tb && !acc)  sgemm_k<true,  false><<<g, b>>>(A, B, C, M, N, K, lda, ldb, ldc, sA, sB, sC, alpha);
    else                  sgemm_k<true,  true ><<<g, b>>>(A, B, C, M, N, K, lda, ldb, ldc, sA, sB, sC, alpha);
}

static void run_attn(float* x, float* outC, bool acc, int S,
                     const float* cs, const float* sn, const float* ln,
                     const float* wq, const float* wk, const float* wv, const float* wo,
                     float* XN, float* Q, float* Kb, float* Vb, float* AO, float* SC)
{
    rmsnorm_k<<<S, 256>>>(x, ln, XN);
    gemm(false, false, XN, wq, Q,  S, D_, D_, D_, D_, D_, 0, 0, 0, 1, 1.f);
    gemm(false, false, XN, wk, Kb, S, D_, D_, D_, D_, D_, 0, 0, 0, 1, 1.f);
    gemm(false, false, XN, wv, Vb, S, D_, D_, D_, D_, D_, 0, 0, 0, 1, 1.f);
    rope_k<<<S, H_ * 32>>>(Q, Kb, cs, sn);
    // scores: per-head Q_h (SxHD, lda=D) @ K_h^T   alpha = 1/sqrt(HD)
    gemm(true, false, Q, Kb, SC, S, S, HD_, D_, D_, S, HD_, HD_, (long long)S * S, H_, 0.125f);
    softmax_causal_k<<<dim3(S, H_), 256>>>(SC, S);
    // PV: per-head P (SxS) @ V_h (SxHD, ldb=D)
    gemm(false, false, SC, Vb, AO, S, HD_, S, S, D_, D_, (long long)S * S, HD_, HD_, H_, 1.f);
    if (acc) gemm(false, true,  AO, wo, x,    S, D_, D_, D_, D_, D_, 0, 0, 0, 1, 1.f);
    else     gemm(false, false, AO, wo, outC, S, D_, D_, D_, D_, D_, 0, 0, 0, 1, 1.f);
}

static void run_ffn(float* x, float* outC, bool acc, int S,
                    const float* ln, const float* w1, const float* w2,
                    float* XN, float* FF)
{
    rmsnorm_k<<<S, 256>>>(x, ln, XN);
    gemm(false, false, XN, w1, FF, S, DFF_, D_, D_, DFF_, DFF_, 0, 0, 0, 1, 1.f);
    gelu_k<<<2048, 256>>>(FF, (long long)S * DFF_);
    if (acc) gemm(false, true,  FF, w2, x,    S, D_, DFF_, DFF_, D_, D_, 0, 0, 0, 1, 1.f);
    else     gemm(false, false, FF, w2, outC, S, D_, DFF_, DFF_, D_, D_, 0, 0, 0, 1, 1.f);
}

// ---------------- entry point ----------------
extern "C" void kernel_launch(void* const* d_in, const int* in_sizes, int n_in,
                              void* d_out, int out_size)
{
    (void)in_sizes; (void)n_in; (void)out_size;
    const int*   ids     = (const int*)  d_in[0];
    const float* embed   = (const float*)d_in[1];
    const float* routerW = (const float*)d_in[2];
    const float* b_aln   = (const float*)d_in[3];
    const float* b_wq    = (const float*)d_in[4];
    const float* b_wk    = (const float*)d_in[5];
    const float* b_wv    = (const float*)d_in[6];
    const float* b_wo    = (const float*)d_in[7];
    const float* b_fln   = (const float*)d_in[8];
    const float* b_w1    = (const float*)d_in[9];
    const float* b_w2    = (const float*)d_in[10];
    const float* a_ln    = (const float*)d_in[11];
    const float* a_wq    = (const float*)d_in[12];
    const float* a_wk    = (const float*)d_in[13];
    const float* a_wv    = (const float*)d_in[14];
    const float* a_wo    = (const float*)d_in[15];
    const float* f_ln    = (const float*)d_in[16];
    const float* f_w1    = (const float*)d_in[17];
    const float* f_w2    = (const float*)d_in[18];
    const float* ln_out  = (const float*)d_in[19];
    float* out = (float*)d_out;

    float* W = nullptr; int* WI = nullptr; double* WD = nullptr;
    cudaGetSymbolAddress((void**)&W,  g_ws);
    cudaGetSymbolAddress((void**)&WI, g_wsi);
    cudaGetSymbolAddress((void**)&WD, g_wsd);

    float *Hh  = W + OFF_H,   *XN  = W + OFF_XN,  *Q   = W + OFF_Q,
          *Kb  = W + OFF_K,   *Vb  = W + OFF_V,   *AO  = W + OFF_AO,
          *FF  = W + OFF_FFN, *SC  = W + OFF_SC,  *XIN = W + OFF_XIN,
          *EOUT= W + OFF_EOUT,*CS  = W + OFF_COS, *SN  = W + OFF_SIN,
          *CSR = W + OFF_COSR,*SNR = W + OFF_SINR,*LG  = W + OFF_LG,
          *RHO = W + OFF_RHO;
    double *PC = WD + OFF_PC, *PS = WD + OFF_PS;
    int *SEL = WI + IOFF_SEL, *STOK = WI + IOFF_STOK, *TSLOT = WI + IOFF_TSLOT,
        *ECNT = WI + IOFF_ECNT, *EOV = WI + IOFF_EOV;

    // rope tables + prefix sums + embedding
    rope_tab_k<<<T_, HD_>>>(CS, SN);
    prefix_k<<<1, HD_>>>(CS, SN, PC, PS);
    embed_k<<<T_, 256>>>(ids, embed, Hh);

    // backbone
    run_attn(Hh, nullptr, true, T_, CS, SN, b_aln, b_wq, b_wk, b_wv, b_wo,
             XN, Q, Kb, Vb, AO, SC);
    run_ffn(Hh, nullptr, true, T_, b_fln, b_w1, b_w2, XN, FF);

    static const int AI[4] = {0, 2, 4, 6};
    static const int FI[4] = {1, 3, 5, 7};

    for (int r = 0; r < NHOPS_; r++) {
        // router logits: h @ router_W[r]^T  (T x 9)
        gemm(true, false, Hh, routerW + (size_t)r * 9 * D_, LG,
             T_, 9, D_, D_, D_, 9, 0, 0, 0, 1, 1.f);
        top2_k<<<(T_ + 255) / 256, 256>>>(LG, SEL, RHO);
        clear_k<<<(9 * CAP_ + 255) / 256, 256>>>(STOK, 9 * CAP_);
        scan_k<<<1, 32>>>(SEL, STOK, TSLOT, ECNT, EOV);
        gather_k<<<8 * CAP_, 256>>>(Hh, STOK, XIN);
        fill_cossin_k<<<8 * CAP_, HD_>>>(STOK, ECNT, EOV, PC, PS, CSR, SNR);

        // attention experts: EOUT[j] = attn_j(xin[AIDX[j]])
        for (int j = 0; j < 4; j++) {
            run_attn(XIN + (size_t)AI[j] * CAP_ * D_,
                     EOUT + (size_t)j * CAP_ * D_, false, CAP_,
                     CSR + (size_t)AI[j] * CAP_ * HD_,
                     SNR + (size_t)AI[j] * CAP_ * HD_,
                     a_ln + (size_t)j * D_,
                     a_wq + (size_t)j * D_ * D_, a_wk + (size_t)j * D_ * D_,
                     a_wv + (size_t)j * D_ * D_, a_wo + (size_t)j * D_ * D_,
                     XN, Q, Kb, Vb, AO, SC);
        }
        // ffn experts: EOUT[4+j] = ffn_j(xin[FIDX[j]])
        for (int j = 0; j < 4; j++) {
            run_ffn(XIN + (size_t)FI[j] * CAP_ * D_,
                    EOUT + (size_t)(4 + j) * CAP_ * D_, false, CAP_,
                    f_ln + (size_t)j * D_,
                    f_w1 + (size_t)j * D_ * DFF_, f_w2 + (size_t)j * DFF_ * D_,
                    XN, FF);
        }

        // h = (1 - rho) * h + combine
        scale_k<<<T_, 256>>>(Hh, RHO);
        combine_k<<<T_, 256>>>(Hh, EOUT, SEL, TSLOT);
    }

    // final: rms(h)*ln_out @ embed^T
    rmsnorm_k<<<T_, 256>>>(Hh, ln_out, XN);
    gemm(true, false, XN, embed, out, T_, V_, D_, D_, D_, V_, 0, 0, 0, 1, 1.f);
}